// round 1
// baseline (speedup 1.0000x reference)
#include <cuda_runtime.h>
#include <math.h>

#define HSZ 1024
#define NH 16
#define DH 64
#define SEQ 2048
#define NB 2
#define MTOT (NB*SEQ)

// Scratch for Q/K/V in [B, h, S, dh] layout (static device globals: allowed).
__device__ float g_q[(size_t)MTOT * HSZ];
__device__ float g_k[(size_t)MTOT * HSZ];
__device__ float g_v[(size_t)MTOT * HSZ];

// ---------------------------------------------------------------------------
// Fused QKV GEMM: Y = X @ W + b for W in {Wq, Wk, Wv}, selected by blockIdx.x.
// Tile: BM=64, BN=64, BK=16. 256 threads, 4x4 register micro-tile per thread.
// Output written directly in [B, h, S, dh] layout.
// ---------------------------------------------------------------------------
__global__ __launch_bounds__(256) void qkv_gemm_kernel(
    const float* __restrict__ X,
    const float* __restrict__ Wq, const float* __restrict__ bq,
    const float* __restrict__ Wk, const float* __restrict__ bk,
    const float* __restrict__ Wv, const float* __restrict__ bv)
{
    __shared__ float Xs[16][64];   // [k][m] (transposed)
    __shared__ float Ws[16][64];   // [k][n]

    const int tid = threadIdx.x;
    const int tx = tid & 15;
    const int ty = tid >> 4;

    const int nblk  = blockIdx.x;          // 0..47
    const int which = nblk >> 4;           // 0=Q, 1=K, 2=V
    const int n0    = (nblk & 15) * 64;    // column offset within 1024
    const int m0    = blockIdx.y * 64;

    const float* W    = (which == 0) ? Wq : (which == 1) ? Wk : Wv;
    const float* bias = (which == 0) ? bq : (which == 1) ? bk : bv;
    float*       dst  = (which == 0) ? g_q : (which == 1) ? g_k : g_v;

    // loader index maps
    const int xm  = tid >> 2;          // 0..63 (row of X tile)
    const int xk4 = (tid & 3) * 4;     // 0,4,8,12
    const int wk  = tid >> 4;          // 0..15 (row of W tile)
    const int wn4 = (tid & 15) * 4;

    float acc[4][4];
#pragma unroll
    for (int i = 0; i < 4; i++)
#pragma unroll
        for (int j = 0; j < 4; j++) acc[i][j] = 0.0f;

    for (int k0 = 0; k0 < HSZ; k0 += 16) {
        float4 xv = *(const float4*)&X[(size_t)(m0 + xm) * HSZ + k0 + xk4];
        float4 wv = *(const float4*)&W[(size_t)(k0 + wk) * HSZ + n0 + wn4];
        __syncthreads();
        Xs[xk4 + 0][xm] = xv.x;
        Xs[xk4 + 1][xm] = xv.y;
        Xs[xk4 + 2][xm] = xv.z;
        Xs[xk4 + 3][xm] = xv.w;
        *(float4*)&Ws[wk][wn4] = wv;
        __syncthreads();

#pragma unroll
        for (int kk = 0; kk < 16; kk++) {
            float4 a = *(const float4*)&Xs[kk][ty * 4];
            float4 b = *(const float4*)&Ws[kk][tx * 4];
            float av[4] = {a.x, a.y, a.z, a.w};
            float bv4[4] = {b.x, b.y, b.z, b.w};
#pragma unroll
            for (int i = 0; i < 4; i++)
#pragma unroll
                for (int j = 0; j < 4; j++)
                    acc[i][j] = fmaf(av[i], bv4[j], acc[i][j]);
        }
    }

    // Epilogue: add bias, store into [B, h, S, dh] scratch. Tile spans a
    // single head (n0 is a multiple of 64), d = tx*4 + j.
    float4 bb = *(const float4*)&bias[n0 + tx * 4];
    const int h = n0 >> 6;
#pragma unroll
    for (int i = 0; i < 4; i++) {
        int m = m0 + ty * 4 + i;
        int b_ = m >> 11;            // m / SEQ
        int s  = m & (SEQ - 1);
        float4 o;
        o.x = acc[i][0] + bb.x;
        o.y = acc[i][1] + bb.y;
        o.z = acc[i][2] + bb.z;
        o.w = acc[i][3] + bb.w;
        *(float4*)&dst[(((size_t)(b_ * NH + h)) * SEQ + s) * DH + tx * 4] = o;
    }
}

// ---------------------------------------------------------------------------
// Flash attention (fp32, online softmax).
// One CTA per (b*h, q-tile of 64 rows). Bc = 64. 256 threads, 4x4 micro-tiles.
// Row stats (m, l) kept redundantly in registers by all 16 threads of a row
// group (identical values -> no smem races). P tile overlays the K tile
// buffer so static smem is exactly 48 KB.
// ---------------------------------------------------------------------------
__global__ __launch_bounds__(256) void attn_kernel(
    const float* __restrict__ mask, float* __restrict__ out)
{
    __shared__ float Qt[64 * 64];    // [d][r]
    __shared__ float KPt[64 * 64];   // K phase: [d][c]; P phase: [c][r]
    __shared__ float Vs[64 * 64];    // [c][d]

    const int tid = threadIdx.x;
    const int tx = tid & 15;
    const int ty = tid >> 4;

    const int bh = blockIdx.y;        // 0..31
    const int b  = bh >> 4;
    const int h  = bh & 15;
    const int q0 = blockIdx.x * 64;

    const float* qg   = g_q + ((size_t)bh * SEQ + q0) * DH;
    const float* kgb  = g_k + (size_t)bh * SEQ * DH;
    const float* vgb  = g_v + (size_t)bh * SEQ * DH;
    const float* mrow = mask + (size_t)b * SEQ;

    // Load Q tile transposed into smem: Qt[d][r]
    {
        int r  = tid >> 2;
        int d0 = (tid & 3) * 16;
#pragma unroll
        for (int u = 0; u < 4; u++) {
            float4 v = *(const float4*)&qg[(size_t)r * DH + d0 + u * 4];
            Qt[(d0 + u * 4 + 0) * 64 + r] = v.x;
            Qt[(d0 + u * 4 + 1) * 64 + r] = v.y;
            Qt[(d0 + u * 4 + 2) * 64 + r] = v.z;
            Qt[(d0 + u * 4 + 3) * 64 + r] = v.w;
        }
    }

    float o[4][4];
    float mrun[4], lrun[4];
#pragma unroll
    for (int i = 0; i < 4; i++) {
        mrun[i] = -INFINITY;
        lrun[i] = 0.0f;
#pragma unroll
        for (int j = 0; j < 4; j++) o[i][j] = 0.0f;
    }

    const unsigned FULL = 0xffffffffu;

    for (int k0 = 0; k0 < SEQ; k0 += 64) {
        __syncthreads();   // previous P@V done before overwriting KPt / Vs

        // Load K tile transposed: KPt[d][c]; V tile straight: Vs[c][d]
        {
            int c  = tid >> 2;
            int d0 = (tid & 3) * 16;
            const float* kg = kgb + (size_t)k0 * DH;
#pragma unroll
            for (int u = 0; u < 4; u++) {
                float4 v = *(const float4*)&kg[(size_t)c * DH + d0 + u * 4];
                KPt[(d0 + u * 4 + 0) * 64 + c] = v.x;
                KPt[(d0 + u * 4 + 1) * 64 + c] = v.y;
                KPt[(d0 + u * 4 + 2) * 64 + c] = v.z;
                KPt[(d0 + u * 4 + 3) * 64 + c] = v.w;
            }
            const float* vg = vgb + (size_t)k0 * DH;
#pragma unroll
            for (int u = 0; u < 4; u++) {
                int off = tid * 4 + u * 1024;
                *(float4*)&Vs[off] = *(const float4*)&vg[off];
            }
        }
        __syncthreads();

        // S = Q K^T  (64x64x64), 4x4 per thread
        float sacc[4][4];
#pragma unroll
        for (int i = 0; i < 4; i++)
#pragma unroll
            for (int j = 0; j < 4; j++) sacc[i][j] = 0.0f;

#pragma unroll 16
        for (int d = 0; d < 64; d++) {
            float4 a = *(const float4*)&Qt[d * 64 + ty * 4];
            float4 k = *(const float4*)&KPt[d * 64 + tx * 4];
            float av[4] = {a.x, a.y, a.z, a.w};
            float kv[4] = {k.x, k.y, k.z, k.w};
#pragma unroll
            for (int i = 0; i < 4; i++)
#pragma unroll
                for (int j = 0; j < 4; j++)
                    sacc[i][j] = fmaf(av[i], kv[j], sacc[i][j]);
        }

        // scale + additive mask (mask depends only on key position)
        float mk[4];
#pragma unroll
        for (int j = 0; j < 4; j++) mk[j] = mrow[k0 + tx * 4 + j];
#pragma unroll
        for (int i = 0; i < 4; i++)
#pragma unroll
            for (int j = 0; j < 4; j++)
                sacc[i][j] = sacc[i][j] * 0.125f + mk[j];

        // online softmax update (per row i; redundant across the 16 tx threads)
        float alpha[4];
#pragma unroll
        for (int i = 0; i < 4; i++) {
            float rm = fmaxf(fmaxf(sacc[i][0], sacc[i][1]),
                             fmaxf(sacc[i][2], sacc[i][3]));
#pragma unroll
            for (int off = 1; off < 16; off <<= 1)
                rm = fmaxf(rm, __shfl_xor_sync(FULL, rm, off));
            float mnew = fmaxf(mrun[i], rm);
            float al = __expf(mrun[i] - mnew);
            float rs = 0.0f;
#pragma unroll
            for (int j = 0; j < 4; j++) {
                sacc[i][j] = __expf(sacc[i][j] - mnew);  // sacc becomes P
                rs += sacc[i][j];
            }
#pragma unroll
            for (int off = 1; off < 16; off <<= 1)
                rs += __shfl_xor_sync(FULL, rs, off);
            lrun[i] = al * lrun[i] + rs;
            mrun[i] = mnew;
            alpha[i] = al;
#pragma unroll
            for (int j = 0; j < 4; j++) o[i][j] *= al;
        }

        __syncthreads();   // everyone done reading KPt (K phase)

        // write P transposed into KPt: KPt[c][r]
#pragma unroll
        for (int j = 0; j < 4; j++)
#pragma unroll
            for (int i = 0; i < 4; i++)
                KPt[(tx * 4 + j) * 64 + ty * 4 + i] = sacc[i][j];
        __syncthreads();

        // O += P @ V
#pragma unroll 16
        for (int c = 0; c < 64; c++) {
            float4 p = *(const float4*)&KPt[c * 64 + ty * 4];
            float4 v = *(const float4*)&Vs[c * 64 + tx * 4];
            float pv[4] = {p.x, p.y, p.z, p.w};
            float vv[4] = {v.x, v.y, v.z, v.w};
#pragma unroll
            for (int i = 0; i < 4; i++)
#pragma unroll
                for (int j = 0; j < 4; j++)
                    o[i][j] = fmaf(pv[i], vv[j], o[i][j]);
        }
    }

    // Epilogue: normalize and write [B, S, h*dh]
#pragma unroll
    for (int i = 0; i < 4; i++) {
        float inv = 1.0f / lrun[i];
        int s = q0 + ty * 4 + i;
        float4 ov;
        ov.x = o[i][0] * inv;
        ov.y = o[i][1] * inv;
        ov.z = o[i][2] * inv;
        ov.w = o[i][3] * inv;
        *(float4*)&out[((size_t)b * SEQ + s) * HSZ + h * DH + tx * 4] = ov;
    }
}

extern "C" void kernel_launch(void* const* d_in, const int* in_sizes, int n_in,
                              void* d_out, int out_size)
{
    const float* hidden = (const float*)d_in[0];
    const float* mask   = (const float*)d_in[1];
    const float* Wq     = (const float*)d_in[2];
    const float* bq     = (const float*)d_in[3];
    const float* Wk     = (const float*)d_in[4];
    const float* bk     = (const float*)d_in[5];
    const float* Wv     = (const float*)d_in[6];
    const float* bv     = (const float*)d_in[7];
    float* out = (float*)d_out;

    dim3 g1(48, 64);               // 3 matrices * 16 n-tiles, 64 m-tiles
    qkv_gemm_kernel<<<g1, 256>>>(hidden, Wq, bq, Wk, bk, Wv, bv);

    dim3 g2(SEQ / 64, NB * NH);    // 32 q-tiles x 32 (b,h)
    attn_kernel<<<g2, 256>>>(mask, out);
}

// round 2
// speedup vs baseline: 1.0283x; 1.0283x over previous
#include <cuda_runtime.h>
#include <math.h>

#define HSZ 1024
#define NH 16
#define DH 64
#define SEQ 2048
#define NB 2
#define MTOT (NB*SEQ)

// Scratch for Q/K/V in [B, h, S, dh] layout.
__device__ float g_q[(size_t)MTOT * HSZ];
__device__ float g_k[(size_t)MTOT * HSZ];
__device__ float g_v[(size_t)MTOT * HSZ];

// ---------------------------------------------------------------------------
// Fused QKV GEMM: BM=128, BN=128, BK=16, 256 threads, 8x8 micro-tile,
// register prefetch of the next K-slab. Output in [B,h,S,dh] layout.
// ---------------------------------------------------------------------------
__global__ __launch_bounds__(256, 2) void qkv_gemm_kernel(
    const float* __restrict__ X,
    const float* __restrict__ Wq, const float* __restrict__ bq,
    const float* __restrict__ Wk, const float* __restrict__ bk,
    const float* __restrict__ Wv, const float* __restrict__ bv)
{
    __shared__ float Xs[16][128];   // [k][m]
    __shared__ float Ws[16][128];   // [k][n]

    const int tid = threadIdx.x;
    const int tx = tid & 15;
    const int ty = tid >> 4;

    const int nblk  = blockIdx.x;          // 0..23
    const int which = nblk >> 3;           // 0=Q,1=K,2=V
    const int n0    = (nblk & 7) * 128;
    const int m0    = blockIdx.y * 128;

    const float* W    = (which == 0) ? Wq : (which == 1) ? Wk : Wv;
    const float* bias = (which == 0) ? bq : (which == 1) ? bk : bv;
    float*       dst  = (which == 0) ? g_q : (which == 1) ? g_k : g_v;

    // loader maps
    const int xr = tid >> 1;           // 0..127 row of X tile
    const int xk = (tid & 1) * 8;      // k base 0 or 8
    const int wr = tid >> 4;           // 0..15 row of W tile
    const int wc = (tid & 15) * 8;     // 0..120

    const float* Xp = X + (size_t)(m0 + xr) * HSZ + xk;
    const float* Wp = W + (size_t)wr * HSZ + n0 + wc;

    float4 x0 = *(const float4*)(Xp);
    float4 x1 = *(const float4*)(Xp + 4);
    float4 w0 = *(const float4*)(Wp);
    float4 w1 = *(const float4*)(Wp + 4);

    float acc[8][8];
#pragma unroll
    for (int i = 0; i < 8; i++)
#pragma unroll
        for (int j = 0; j < 8; j++) acc[i][j] = 0.0f;

    for (int k0 = 0; k0 < HSZ; k0 += 16) {
        __syncthreads();
        Xs[xk + 0][xr] = x0.x;
        Xs[xk + 1][xr] = x0.y;
        Xs[xk + 2][xr] = x0.z;
        Xs[xk + 3][xr] = x0.w;
        Xs[xk + 4][xr] = x1.x;
        Xs[xk + 5][xr] = x1.y;
        Xs[xk + 6][xr] = x1.z;
        Xs[xk + 7][xr] = x1.w;
        *(float4*)&Ws[wr][wc]     = w0;
        *(float4*)&Ws[wr][wc + 4] = w1;
        __syncthreads();

        if (k0 + 16 < HSZ) {
            x0 = *(const float4*)(Xp + k0 + 16);
            x1 = *(const float4*)(Xp + k0 + 20);
            w0 = *(const float4*)(Wp + (size_t)(k0 + 16) * HSZ);
            w1 = *(const float4*)(Wp + (size_t)(k0 + 16) * HSZ + 4);
        }

#pragma unroll
        for (int kk = 0; kk < 16; kk++) {
            float4 a0 = *(const float4*)&Xs[kk][ty * 8];
            float4 a1 = *(const float4*)&Xs[kk][ty * 8 + 4];
            float4 b0 = *(const float4*)&Ws[kk][tx * 8];
            float4 b1 = *(const float4*)&Ws[kk][tx * 8 + 4];
            float av[8] = {a0.x, a0.y, a0.z, a0.w, a1.x, a1.y, a1.z, a1.w};
            float bv4[8] = {b0.x, b0.y, b0.z, b0.w, b1.x, b1.y, b1.z, b1.w};
#pragma unroll
            for (int i = 0; i < 8; i++)
#pragma unroll
                for (int j = 0; j < 8; j++)
                    acc[i][j] = fmaf(av[i], bv4[j], acc[i][j]);
        }
    }

    // epilogue: bias + store. 8-col block never crosses a head boundary.
    const int cb = n0 + tx * 8;
    const int h  = cb >> 6;
    const int d0 = cb & 63;
    float4 bb0 = *(const float4*)&bias[cb];
    float4 bb1 = *(const float4*)&bias[cb + 4];
#pragma unroll
    for (int i = 0; i < 8; i++) {
        int m  = m0 + ty * 8 + i;
        int b_ = m >> 11;
        int s  = m & (SEQ - 1);
        float* drow = dst + (((size_t)(b_ * NH + h)) * SEQ + s) * DH + d0;
        float4 o0, o1;
        o0.x = acc[i][0] + bb0.x; o0.y = acc[i][1] + bb0.y;
        o0.z = acc[i][2] + bb0.z; o0.w = acc[i][3] + bb0.w;
        o1.x = acc[i][4] + bb1.x; o1.y = acc[i][5] + bb1.y;
        o1.z = acc[i][6] + bb1.z; o1.w = acc[i][7] + bb1.w;
        *(float4*)(drow)     = o0;
        *(float4*)(drow + 4) = o1;
    }
}

// ---------------------------------------------------------------------------
// Flash attention fp32: Br=128, Bc=128, 256 threads.
// S micro-tile 8x8, O micro-tile 8x4. Dynamic smem 128KB:
//   Qt [64][128]   (floats 0..8191)     — Q transposed, loaded once
//   Vs [128][64]   (floats 8192..16383)
//   KP [16384 fl]  (floats 16384..32767) — K transposed [64][128] during S,
//                                          then P transposed [128][128] w/ swizzle
// ---------------------------------------------------------------------------
extern __shared__ float sm_attn[];

__global__ __launch_bounds__(256, 1) void attn_kernel(
    const float* __restrict__ mask, float* __restrict__ out)
{
    float* Qt = sm_attn;             // [d][r] stride 128
    float* Vs = sm_attn + 8192;      // [c][d] stride 64
    float* KP = sm_attn + 16384;     // K: [d][c] stride 128 ; P: c*128 + rot(r)

    const int tid = threadIdx.x;
    const int tx = tid & 15;
    const int ty = tid >> 4;

    const int bh = blockIdx.y;
    const int b  = bh >> 4;
    const int h  = bh & 15;
    const int q0 = blockIdx.x * 128;

    const float* qg   = g_q + ((size_t)bh * SEQ + q0) * DH;
    const float* kgb  = g_k + (size_t)bh * SEQ * DH;
    const float* vgb  = g_v + (size_t)bh * SEQ * DH;
    const float* mrow = mask + (size_t)b * SEQ;

    // Load Q transposed (once)
    {
        int r  = tid >> 1;
        int c0 = (tid & 1) * 32;
#pragma unroll
        for (int u = 0; u < 8; u++) {
            float4 v = *(const float4*)&qg[(size_t)r * DH + c0 + u * 4];
            Qt[(c0 + u * 4 + 0) * 128 + r] = v.x;
            Qt[(c0 + u * 4 + 1) * 128 + r] = v.y;
            Qt[(c0 + u * 4 + 2) * 128 + r] = v.z;
            Qt[(c0 + u * 4 + 3) * 128 + r] = v.w;
        }
    }

    float o[8][4];
    float mrun[8], lrun[8];
#pragma unroll
    for (int i = 0; i < 8; i++) {
        mrun[i] = -INFINITY;
        lrun[i] = 0.0f;
#pragma unroll
        for (int j = 0; j < 4; j++) o[i][j] = 0.0f;
    }

    const unsigned FULL = 0xffffffffu;

    for (int k0 = 0; k0 < SEQ; k0 += 128) {
        __syncthreads();   // prev PV done; safe to overwrite KP & Vs

        // K transposed into KP, V straight into Vs
        {
            int r  = tid >> 1;            // key index 0..127
            int c0 = (tid & 1) * 32;      // d base
            const float* kg = kgb + (size_t)(k0 + r) * DH + c0;
#pragma unroll
            for (int u = 0; u < 8; u++) {
                float4 v = *(const float4*)(kg + u * 4);
                KP[(c0 + u * 4 + 0) * 128 + r] = v.x;
                KP[(c0 + u * 4 + 1) * 128 + r] = v.y;
                KP[(c0 + u * 4 + 2) * 128 + r] = v.z;
                KP[(c0 + u * 4 + 3) * 128 + r] = v.w;
            }
            const float* vg = vgb + (size_t)k0 * DH;
#pragma unroll
            for (int u = 0; u < 8; u++) {
                int off = tid * 4 + u * 1024;
                *(float4*)&Vs[off] = *(const float4*)(vg + off);
            }
        }
        __syncthreads();

        // S = Q K^T : 128x128, micro 8x8
        float sacc[8][8];
#pragma unroll
        for (int i = 0; i < 8; i++)
#pragma unroll
            for (int j = 0; j < 8; j++) sacc[i][j] = 0.0f;

#pragma unroll 4
        for (int d = 0; d < 64; d++) {
            float4 a0 = *(const float4*)&Qt[d * 128 + ty * 8];
            float4 a1 = *(const float4*)&Qt[d * 128 + ty * 8 + 4];
            float4 b0 = *(const float4*)&KP[d * 128 + tx * 8];
            float4 b1 = *(const float4*)&KP[d * 128 + tx * 8 + 4];
            float av[8] = {a0.x, a0.y, a0.z, a0.w, a1.x, a1.y, a1.z, a1.w};
            float kv[8] = {b0.x, b0.y, b0.z, b0.w, b1.x, b1.y, b1.z, b1.w};
#pragma unroll
            for (int i = 0; i < 8; i++)
#pragma unroll
                for (int j = 0; j < 8; j++)
                    sacc[i][j] = fmaf(av[i], kv[j], sacc[i][j]);
        }

        // scale + additive mask (depends only on key position)
        {
            float4 m0v = *(const float4*)&mrow[k0 + tx * 8];
            float4 m1v = *(const float4*)&mrow[k0 + tx * 8 + 4];
            float mk[8] = {m0v.x, m0v.y, m0v.z, m0v.w, m1v.x, m1v.y, m1v.z, m1v.w};
#pragma unroll
            for (int i = 0; i < 8; i++)
#pragma unroll
                for (int j = 0; j < 8; j++)
                    sacc[i][j] = sacc[i][j] * 0.125f + mk[j];
        }

        // online softmax (row-group = 16 tx lanes, within one warp half)
#pragma unroll
        for (int i = 0; i < 8; i++) {
            float rm = sacc[i][0];
#pragma unroll
            for (int j = 1; j < 8; j++) rm = fmaxf(rm, sacc[i][j]);
#pragma unroll
            for (int off = 1; off < 16; off <<= 1)
                rm = fmaxf(rm, __shfl_xor_sync(FULL, rm, off));
            float mnew = fmaxf(mrun[i], rm);
            float al = __expf(mrun[i] - mnew);
            float rs = 0.0f;
#pragma unroll
            for (int j = 0; j < 8; j++) {
                sacc[i][j] = __expf(sacc[i][j] - mnew);
                rs += sacc[i][j];
            }
#pragma unroll
            for (int off = 1; off < 16; off <<= 1)
                rs += __shfl_xor_sync(FULL, rs, off);
            lrun[i] = al * lrun[i] + rs;
            mrun[i] = mnew;
#pragma unroll
            for (int j = 0; j < 4; j++) o[i][j] *= al;
        }

        __syncthreads();   // done reading K from KP

        // store P transposed: KP[c*128 + rot(r)], rot = (r + 8*(c&15)) & 127
#pragma unroll
        for (int j = 0; j < 8; j++) {
            int c = tx * 8 + j;
            int rbase = (ty * 8 + ((c & 15) << 3)) & 127;
            float* p = &KP[c * 128 + rbase];
            float4 p0, p1;
            p0.x = sacc[0][j]; p0.y = sacc[1][j]; p0.z = sacc[2][j]; p0.w = sacc[3][j];
            p1.x = sacc[4][j]; p1.y = sacc[5][j]; p1.z = sacc[6][j]; p1.w = sacc[7][j];
            *(float4*)(p)     = p0;
            *(float4*)(p + 4) = p1;
        }
        __syncthreads();

        // O += P @ V : micro 8 rows x 4 d-cols
#pragma unroll 4
        for (int c = 0; c < 128; c++) {
            int rbase = (ty * 8 + ((c & 15) << 3)) & 127;
            float4 p0 = *(const float4*)&KP[c * 128 + rbase];
            float4 p1 = *(const float4*)&KP[c * 128 + rbase + 4];
            float4 v  = *(const float4*)&Vs[c * 64 + tx * 4];
            float pv[8] = {p0.x, p0.y, p0.z, p0.w, p1.x, p1.y, p1.z, p1.w};
            float vv[4] = {v.x, v.y, v.z, v.w};
#pragma unroll
            for (int i = 0; i < 8; i++)
#pragma unroll
                for (int j = 0; j < 4; j++)
                    o[i][j] = fmaf(pv[i], vv[j], o[i][j]);
        }
    }

    // epilogue: normalize, write [B,S,hidden]
#pragma unroll
    for (int i = 0; i < 8; i++) {
        float inv = 1.0f / lrun[i];
        int s = q0 + ty * 8 + i;
        float4 ov;
        ov.x = o[i][0] * inv;
        ov.y = o[i][1] * inv;
        ov.z = o[i][2] * inv;
        ov.w = o[i][3] * inv;
        *(float4*)&out[((size_t)b * SEQ + s) * HSZ + h * DH + tx * 4] = ov;
    }
}

extern "C" void kernel_launch(void* const* d_in, const int* in_sizes, int n_in,
                              void* d_out, int out_size)
{
    const float* hidden = (const float*)d_in[0];
    const float* mask   = (const float*)d_in[1];
    const float* Wq     = (const float*)d_in[2];
    const float* bq     = (const float*)d_in[3];
    const float* Wk     = (const float*)d_in[4];
    const float* bk     = (const float*)d_in[5];
    const float* Wv     = (const float*)d_in[6];
    const float* bv     = (const float*)d_in[7];
    float* out = (float*)d_out;

    dim3 g1(24, 32);               // 3 matrices * 8 n-tiles, 32 m-tiles
    qkv_gemm_kernel<<<g1, 256>>>(hidden, Wq, bq, Wk, bk, Wv, bv);

    const int ATTN_SMEM = 32768 * sizeof(float);   // 128 KB
    cudaFuncSetAttribute(attn_kernel,
                         cudaFuncAttributeMaxDynamicSharedMemorySize, ATTN_SMEM);
    dim3 g2(SEQ / 128, NB * NH);   // 16 q-tiles x 32 (b,h)
    attn_kernel<<<g2, 256, ATTN_SMEM>>>(mask, out);
}

// round 6
// speedup vs baseline: 2.3894x; 2.3237x over previous
#include <cuda_runtime.h>
#include <cuda_bf16.h>
#include <math.h>
#include <stdint.h>

#define HSZ 1024
#define NH 16
#define DH 64
#define SEQ 2048
#define NB 2
#define MTOT (NB*SEQ)
#define LOG2E 1.4426950408889634f
#define QSCALE (0.125f * LOG2E)

// split-bf16 GEMM inputs
__device__ __nv_bfloat16 g_xh[(size_t)MTOT * HSZ];
__device__ __nv_bfloat16 g_xl[(size_t)MTOT * HSZ];
__device__ __nv_bfloat16 g_wh[3 * (size_t)HSZ * HSZ];   // transposed [n][k]
__device__ __nv_bfloat16 g_wl[3 * (size_t)HSZ * HSZ];
// attention operands: Q/K hi+lo in [bh][s][d]; V hi+lo transposed [bh][d][s]
__device__ __nv_bfloat16 g_qh[(size_t)MTOT * HSZ];
__device__ __nv_bfloat16 g_ql[(size_t)MTOT * HSZ];
__device__ __nv_bfloat16 g_kh[(size_t)MTOT * HSZ];
__device__ __nv_bfloat16 g_kl[(size_t)MTOT * HSZ];
__device__ __nv_bfloat16 g_vth[(size_t)MTOT * HSZ];
__device__ __nv_bfloat16 g_vtl[(size_t)MTOT * HSZ];

// ---------------------------------------------------------------------------
// mma.sync m16n8k16 bf16 helpers
// ---------------------------------------------------------------------------
__device__ __forceinline__ void mma_bf16(float d[4], const uint32_t a[4],
                                         const uint32_t b[2]) {
    asm volatile(
        "mma.sync.aligned.m16n8k16.row.col.f32.bf16.bf16.f32 "
        "{%0,%1,%2,%3}, {%4,%5,%6,%7}, {%8,%9}, {%0,%1,%2,%3};\n"
        : "+f"(d[0]), "+f"(d[1]), "+f"(d[2]), "+f"(d[3])
        : "r"(a[0]), "r"(a[1]), "r"(a[2]), "r"(a[3]), "r"(b[0]), "r"(b[1]));
}
__device__ __forceinline__ void ldA(uint32_t a[4], const __nv_bfloat16* base,
                                    int r0, int k0, int stride, int lane) {
    const __nv_bfloat16* p = base + (size_t)(r0 + (lane >> 2)) * stride + k0 + ((lane & 3) << 1);
    a[0] = *(const uint32_t*)p;
    a[1] = *(const uint32_t*)(p + 8 * stride);
    a[2] = *(const uint32_t*)(p + 8);
    a[3] = *(const uint32_t*)(p + 8 * stride + 8);
}
__device__ __forceinline__ void ldB(uint32_t b[2], const __nv_bfloat16* base,
                                    int n0, int k0, int stride, int lane) {
    const __nv_bfloat16* p = base + (size_t)(n0 + (lane >> 2)) * stride + k0 + ((lane & 3) << 1);
    b[0] = *(const uint32_t*)p;
    b[1] = *(const uint32_t*)(p + 8);
}
__device__ __forceinline__ float ex2f(float x) {
    float y;
    asm("ex2.approx.ftz.f32 %0, %1;" : "=f"(y) : "f"(x));
    return y;
}
// pack two fp32 -> bf16x2 (lo in lower half)
__device__ __forceinline__ uint32_t packbf(float lo, float hi) {
    uint32_t r;
    asm("cvt.rn.bf16x2.f32 %0, %1, %2;" : "=r"(r) : "f"(hi), "f"(lo));
    return r;
}

// ---------------------------------------------------------------------------
// Split hidden_states into bf16 hi/lo
// ---------------------------------------------------------------------------
__global__ __launch_bounds__(256) void split_x_kernel(const float* __restrict__ X)
{
    size_t i = ((size_t)blockIdx.x * 256 + threadIdx.x) * 4;
    float4 v = *(const float4*)(X + i);
    float f[4] = {v.x, v.y, v.z, v.w};
#pragma unroll
    for (int u = 0; u < 4; u++) {
        __nv_bfloat16 h = __float2bfloat16(f[u]);
        g_xh[i + u] = h;
        g_xl[i + u] = __float2bfloat16(f[u] - __bfloat162float(h));
    }
}

// ---------------------------------------------------------------------------
// Transpose + split weights: Wt[n][k] = W[k][n]
// ---------------------------------------------------------------------------
__global__ __launch_bounds__(256) void split_w_kernel(
    const float* __restrict__ Wq, const float* __restrict__ Wk,
    const float* __restrict__ Wv)
{
    __shared__ float t[32][33];
    const int z = blockIdx.z;
    const float* W = (z == 0) ? Wq : (z == 1) ? Wk : Wv;
    __nv_bfloat16* Th = g_wh + (size_t)z * HSZ * HSZ;
    __nv_bfloat16* Tl = g_wl + (size_t)z * HSZ * HSZ;

    const int n0 = blockIdx.x * 32;
    const int k0 = blockIdx.y * 32;
    const int tx = threadIdx.x & 31;
    const int ty = threadIdx.x >> 5;

#pragma unroll
    for (int j = 0; j < 4; j++) {
        int k = k0 + ty + j * 8;
        t[ty + j * 8][tx] = W[(size_t)k * HSZ + n0 + tx];
    }
    __syncthreads();
#pragma unroll
    for (int j = 0; j < 4; j++) {
        int r = ty + j * 8;
        float v = t[tx][r];
        __nv_bfloat16 h = __float2bfloat16(v);
        size_t o = (size_t)(n0 + r) * HSZ + k0 + tx;
        Th[o] = h;
        Tl[o] = __float2bfloat16(v - __bfloat162float(h));
    }
}

// ---------------------------------------------------------------------------
// QKV GEMM via mma.sync, 3-term split. CTA 128x128, BK=64, 8 warps (4x2).
// ---------------------------------------------------------------------------
extern __shared__ __align__(16) char dsm[];

__global__ __launch_bounds__(256) void qkv_mma_kernel(
    const float* __restrict__ bq, const float* __restrict__ bk,
    const float* __restrict__ bv)
{
    __nv_bfloat16* sh  = (__nv_bfloat16*)dsm;
    __nv_bfloat16* sAh = sh;
    __nv_bfloat16* sAl = sh + 9216;
    __nv_bfloat16* sBh = sh + 18432;
    __nv_bfloat16* sBl = sh + 27648;

    const int tid  = threadIdx.x;
    const int lane = tid & 31;
    const int wid  = tid >> 5;
    const int wr   = wid >> 1;
    const int wc   = wid & 1;

    const int n0  = blockIdx.x * 128;
    const int m0  = blockIdx.y * 128;
    const int mat = blockIdx.z;

    const __nv_bfloat16* Bh = g_wh + (size_t)mat * HSZ * HSZ;
    const __nv_bfloat16* Bl = g_wl + (size_t)mat * HSZ * HSZ;
    const float* bias = (mat == 0) ? bq : (mat == 1) ? bk : bv;

    const int lrow = tid >> 1;
    const int lcb  = (tid & 1) * 32;

    float acc[2][8][4];
#pragma unroll
    for (int i = 0; i < 2; i++)
#pragma unroll
        for (int j = 0; j < 8; j++)
#pragma unroll
            for (int u = 0; u < 4; u++) acc[i][j][u] = 0.0f;

    for (int kc = 0; kc < HSZ / 64; kc++) {
        const int gk = kc * 64;
        __syncthreads();
        {
            const uint4* axh = (const uint4*)(g_xh + (size_t)(m0 + lrow) * HSZ + gk + lcb);
            const uint4* axl = (const uint4*)(g_xl + (size_t)(m0 + lrow) * HSZ + gk + lcb);
            const uint4* bxh = (const uint4*)(Bh + (size_t)(n0 + lrow) * HSZ + gk + lcb);
            const uint4* bxl = (const uint4*)(Bl + (size_t)(n0 + lrow) * HSZ + gk + lcb);
            uint4* dAh = (uint4*)(sAh + lrow * 72 + lcb);
            uint4* dAl = (uint4*)(sAl + lrow * 72 + lcb);
            uint4* dBh = (uint4*)(sBh + lrow * 72 + lcb);
            uint4* dBl = (uint4*)(sBl + lrow * 72 + lcb);
#pragma unroll
            for (int u = 0; u < 4; u++) {
                dAh[u] = axh[u];
                dAl[u] = axl[u];
                dBh[u] = bxh[u];
                dBl[u] = bxl[u];
            }
        }
        __syncthreads();

#pragma unroll
        for (int sp = 0; sp < 3; sp++) {
            const __nv_bfloat16* As = (sp == 1) ? sAl : sAh;
            const __nv_bfloat16* Bs = (sp == 2) ? sBl : sBh;
#pragma unroll
            for (int ks = 0; ks < 4; ks++) {
                uint32_t a0[4], a1[4];
                ldA(a0, As, wr * 32,      ks * 16, 72, lane);
                ldA(a1, As, wr * 32 + 16, ks * 16, 72, lane);
#pragma unroll
                for (int nt = 0; nt < 8; nt++) {
                    uint32_t b[2];
                    ldB(b, Bs, wc * 64 + nt * 8, ks * 16, 72, lane);
                    mma_bf16(acc[0][nt], a0, b);
                    mma_bf16(acc[1][nt], a1, b);
                }
            }
        }
    }

    // epilogue
#pragma unroll
    for (int mt = 0; mt < 2; mt++) {
#pragma unroll
        for (int nt = 0; nt < 8; nt++) {
            int mbase = m0 + wr * 32 + mt * 16 + (lane >> 2);
            int c = n0 + wc * 64 + nt * 8 + ((lane & 3) << 1);
            float b0 = bias[c], b1 = bias[c + 1];
            int hh = c >> 6, d = c & 63;
#pragma unroll
            for (int hf = 0; hf < 2; hf++) {
                int mm = mbase + hf * 8;
                float v0 = acc[mt][nt][hf * 2 + 0] + b0;
                float v1 = acc[mt][nt][hf * 2 + 1] + b1;
                int b_ = mm >> 11, s = mm & (SEQ - 1);
                size_t bh = (size_t)(b_ * NH + hh);
                if (mat == 0) {
                    v0 *= QSCALE;
                    v1 *= QSCALE;
                    __nv_bfloat16 h0 = __float2bfloat16(v0);
                    __nv_bfloat16 h1 = __float2bfloat16(v1);
                    uint32_t hi = ((uint32_t)*(uint16_t*)&h1 << 16) | *(uint16_t*)&h0;
                    uint32_t lo = packbf(v0 - __bfloat162float(h0), v1 - __bfloat162float(h1));
                    size_t o = (bh * SEQ + s) * DH + d;
                    *(uint32_t*)(g_qh + o) = hi;
                    *(uint32_t*)(g_ql + o) = lo;
                } else if (mat == 1) {
                    __nv_bfloat16 h0 = __float2bfloat16(v0);
                    __nv_bfloat16 h1 = __float2bfloat16(v1);
                    uint32_t hi = ((uint32_t)*(uint16_t*)&h1 << 16) | *(uint16_t*)&h0;
                    uint32_t lo = packbf(v0 - __bfloat162float(h0), v1 - __bfloat162float(h1));
                    size_t o = (bh * SEQ + s) * DH + d;
                    *(uint32_t*)(g_kh + o) = hi;
                    *(uint32_t*)(g_kl + o) = lo;
                } else {
                    // V transposed hi/lo: [bh][d][s]
                    __nv_bfloat16 h0 = __float2bfloat16(v0);
                    __nv_bfloat16 h1 = __float2bfloat16(v1);
                    size_t o0 = (bh * DH + d)     * SEQ + s;
                    size_t o1 = (bh * DH + d + 1) * SEQ + s;
                    g_vth[o0] = h0;
                    g_vth[o1] = h1;
                    g_vtl[o0] = __float2bfloat16(v0 - __bfloat162float(h0));
                    g_vtl[o1] = __float2bfloat16(v1 - __bfloat162float(h1));
                }
            }
        }
    }
}

// ---------------------------------------------------------------------------
// Flash attention via mma.sync, split precision everywhere.
// CTA = 128 q-rows (8 warps x 16), Bc = 64, 256 threads.
// ---------------------------------------------------------------------------
__global__ __launch_bounds__(256) void attn_mma_kernel(
    const float* __restrict__ mask, float* __restrict__ out)
{
    __shared__ __nv_bfloat16 sKh[64 * 72];
    __shared__ __nv_bfloat16 sKl[64 * 72];
    __shared__ __nv_bfloat16 sVh[64 * 72];   // [d][s]
    __shared__ __nv_bfloat16 sVl[64 * 72];

    const int tid  = threadIdx.x;
    const int lane = tid & 31;
    const int wid  = tid >> 5;        // 0..7

    const int bh = blockIdx.y;
    const int b  = bh >> 4;
    const int h  = bh & 15;
    const int q0 = blockIdx.x * 128 + wid * 16;

    const float* mrow = mask + (size_t)b * SEQ;

    // Q fragments (hi/lo), 4 k-steps
    uint32_t qh[4][4], ql[4][4];
    {
        const __nv_bfloat16* qbh = g_qh + ((size_t)bh * SEQ + q0) * DH;
        const __nv_bfloat16* qbl = g_ql + ((size_t)bh * SEQ + q0) * DH;
#pragma unroll
        for (int ks = 0; ks < 4; ks++) {
            ldA(qh[ks], qbh, 0, ks * 16, DH, lane);
            ldA(ql[ks], qbl, 0, ks * 16, DH, lane);
        }
    }

    float oacc[8][4];
#pragma unroll
    for (int j = 0; j < 8; j++)
#pragma unroll
        for (int u = 0; u < 4; u++) oacc[j][u] = 0.0f;
    float m1 = -1e30f, m2 = -1e30f, l1 = 0.0f, l2 = 0.0f;

    const int lrow = tid >> 2;          // 0..63
    const int lcb  = (tid & 3) * 16;    // 0,16,32,48

    for (int k0 = 0; k0 < SEQ; k0 += 64) {
        __syncthreads();
        {
            size_t ko = ((size_t)bh * SEQ + k0 + lrow) * DH + lcb;
            size_t vo = ((size_t)bh * DH + lrow) * SEQ + k0 + lcb;
            uint32_t so = lrow * 72 + lcb;
#pragma unroll
            for (int u = 0; u < 2; u++) {
                ((uint4*)(sKh + so))[u] = ((const uint4*)(g_kh + ko))[u];
                ((uint4*)(sKl + so))[u] = ((const uint4*)(g_kl + ko))[u];
                ((uint4*)(sVh + so))[u] = ((const uint4*)(g_vth + vo))[u];
                ((uint4*)(sVl + so))[u] = ((const uint4*)(g_vtl + vo))[u];
            }
        }
        __syncthreads();

        // S = (Qh+Ql) Kh^T + Qh Kl^T   (16 x 64)
        float sacc[8][4];
#pragma unroll
        for (int j = 0; j < 8; j++)
#pragma unroll
            for (int u = 0; u < 4; u++) sacc[j][u] = 0.0f;
#pragma unroll
        for (int ks = 0; ks < 4; ks++) {
#pragma unroll
            for (int nt = 0; nt < 8; nt++) {
                uint32_t bh_[2], bl_[2];
                ldB(bh_, sKh, nt * 8, ks * 16, 72, lane);
                ldB(bl_, sKl, nt * 8, ks * 16, 72, lane);
                mma_bf16(sacc[nt], qh[ks], bh_);
                mma_bf16(sacc[nt], ql[ks], bh_);
                mma_bf16(sacc[nt], qh[ks], bl_);
            }
        }

        // additive mask (log2 domain)
#pragma unroll
        for (int nt = 0; nt < 8; nt++) {
            float2 mk = *(const float2*)&mrow[k0 + nt * 8 + ((lane & 3) << 1)];
            float a0 = mk.x * LOG2E, a1 = mk.y * LOG2E;
            sacc[nt][0] += a0; sacc[nt][1] += a1;
            sacc[nt][2] += a0; sacc[nt][3] += a1;
        }

        // online softmax (rows r and r+8)
        float rm1 = -1e30f, rm2 = -1e30f;
#pragma unroll
        for (int nt = 0; nt < 8; nt++) {
            rm1 = fmaxf(rm1, fmaxf(sacc[nt][0], sacc[nt][1]));
            rm2 = fmaxf(rm2, fmaxf(sacc[nt][2], sacc[nt][3]));
        }
#pragma unroll
        for (int off = 1; off < 4; off <<= 1) {
            rm1 = fmaxf(rm1, __shfl_xor_sync(0xffffffffu, rm1, off));
            rm2 = fmaxf(rm2, __shfl_xor_sync(0xffffffffu, rm2, off));
        }
        float mn1 = fmaxf(m1, rm1);
        float mn2 = fmaxf(m2, rm2);
        float al1 = ex2f(m1 - mn1);
        float al2 = ex2f(m2 - mn2);
        m1 = mn1; m2 = mn2;

        float rs1 = 0.0f, rs2 = 0.0f;
#pragma unroll
        for (int nt = 0; nt < 8; nt++) {
            sacc[nt][0] = ex2f(sacc[nt][0] - mn1);
            sacc[nt][1] = ex2f(sacc[nt][1] - mn1);
            sacc[nt][2] = ex2f(sacc[nt][2] - mn2);
            sacc[nt][3] = ex2f(sacc[nt][3] - mn2);
            rs1 += sacc[nt][0] + sacc[nt][1];
            rs2 += sacc[nt][2] + sacc[nt][3];
        }
#pragma unroll
        for (int off = 1; off < 4; off <<= 1) {
            rs1 += __shfl_xor_sync(0xffffffffu, rs1, off);
            rs2 += __shfl_xor_sync(0xffffffffu, rs2, off);
        }
        l1 = l1 * al1 + rs1;
        l2 = l2 * al2 + rs2;

#pragma unroll
        for (int j = 0; j < 8; j++) {
            oacc[j][0] *= al1; oacc[j][1] *= al1;
            oacc[j][2] *= al2; oacc[j][3] *= al2;
        }

        // O += Ph Vh + Pl Vh + Ph Vl
#pragma unroll
        for (int t = 0; t < 4; t++) {
            uint32_t ah[4], al_[4];
            float p00 = sacc[2*t][0],   p01 = sacc[2*t][1];
            float p02 = sacc[2*t][2],   p03 = sacc[2*t][3];
            float p10 = sacc[2*t+1][0], p11 = sacc[2*t+1][1];
            float p12 = sacc[2*t+1][2], p13 = sacc[2*t+1][3];
            ah[0] = packbf(p00, p01);
            ah[1] = packbf(p02, p03);
            ah[2] = packbf(p10, p11);
            ah[3] = packbf(p12, p13);
            // exact residuals
            __nv_bfloat162 t0 = *(__nv_bfloat162*)&ah[0];
            __nv_bfloat162 t1 = *(__nv_bfloat162*)&ah[1];
            __nv_bfloat162 t2 = *(__nv_bfloat162*)&ah[2];
            __nv_bfloat162 t3 = *(__nv_bfloat162*)&ah[3];
            al_[0] = packbf(p00 - __bfloat162float(t0.x), p01 - __bfloat162float(t0.y));
            al_[1] = packbf(p02 - __bfloat162float(t1.x), p03 - __bfloat162float(t1.y));
            al_[2] = packbf(p10 - __bfloat162float(t2.x), p11 - __bfloat162float(t2.y));
            al_[3] = packbf(p12 - __bfloat162float(t3.x), p13 - __bfloat162float(t3.y));
#pragma unroll
            for (int dt = 0; dt < 8; dt++) {
                uint32_t bvh[2], bvl[2];
                ldB(bvh, sVh, dt * 8, t * 16, 72, lane);
                ldB(bvl, sVl, dt * 8, t * 16, 72, lane);
                mma_bf16(oacc[dt], ah, bvh);
                mma_bf16(oacc[dt], al_, bvh);
                mma_bf16(oacc[dt], ah, bvl);
            }
        }
    }

    // epilogue
    float inv1 = 1.0f / l1;
    float inv2 = 1.0f / l2;
    const int s1 = q0 + (lane >> 2);
    const int s2 = s1 + 8;
#pragma unroll
    for (int dt = 0; dt < 8; dt++) {
        int d = dt * 8 + ((lane & 3) << 1);
        float2 o1, o2;
        o1.x = oacc[dt][0] * inv1; o1.y = oacc[dt][1] * inv1;
        o2.x = oacc[dt][2] * inv2; o2.y = oacc[dt][3] * inv2;
        *(float2*)&out[((size_t)b * SEQ + s1) * HSZ + h * DH + d] = o1;
        *(float2*)&out[((size_t)b * SEQ + s2) * HSZ + h * DH + d] = o2;
    }
}

extern "C" void kernel_launch(void* const* d_in, const int* in_sizes, int n_in,
                              void* d_out, int out_size)
{
    const float* hidden = (const float*)d_in[0];
    const float* mask   = (const float*)d_in[1];
    const float* Wq     = (const float*)d_in[2];
    const float* bq     = (const float*)d_in[3];
    const float* Wk     = (const float*)d_in[4];
    const float* bk     = (const float*)d_in[5];
    const float* Wv     = (const float*)d_in[6];
    const float* bv     = (const float*)d_in[7];
    float* out = (float*)d_out;

    split_x_kernel<<<(MTOT * HSZ) / (256 * 4), 256>>>(hidden);
    split_w_kernel<<<dim3(HSZ / 32, HSZ / 32, 3), 256>>>(Wq, Wk, Wv);

    const int QKV_SMEM = 73728;
    cudaFuncSetAttribute(qkv_mma_kernel,
                         cudaFuncAttributeMaxDynamicSharedMemorySize, QKV_SMEM);
    qkv_mma_kernel<<<dim3(8, 32, 3), 256, QKV_SMEM>>>(bq, bk, bv);

    attn_mma_kernel<<<dim3(SEQ / 128, NB * NH), 256>>>(mask, out);
}